// round 3
// baseline (speedup 1.0000x reference)
#include <cuda_runtime.h>
#include <math.h>

// Problem dims
#define B_DIM   16384
#define Z_DIM   128
#define H_DIM   512
#define HID_DIM 512
#define T_STEPS 32

// Scratch (device globals -- no allocation allowed)
__device__ __align__(256) float g_ctxproj[(size_t)B_DIM * HID_DIM]; // ctx @ W1[Z:,:] + b1
__device__ __align__(256) float g_h[(size_t)B_DIM * HID_DIM];      // hidden activations
__device__ __align__(256) float g_z[(size_t)B_DIM * Z_DIM];        // state z
__device__ __align__(256) float g_logw[(size_t)B_DIM * Z_DIM];     // accumulated log-weights
__device__ double g_sum;

// ---------------- SGEMM tile config ----------------
#define BM 128
#define BN 128
#define BK 16
#define TM 8
#define TN 8
#define NT 256   // (BM/TM)*(BN/TN)

// Computes acc = A[BMxK] @ B[KxBN]; A pre-offset to block row, Bmat pre-offset to block col.
__device__ __forceinline__ void gemm_128x128(
    const float* __restrict__ A, int lda,
    const float* __restrict__ Bmat, int ldb,
    int K, float (&acc)[TM][TN],
    float (*As)[BM], float (*Bs)[BN])
{
    const int tid = threadIdx.x;
    const int tx = tid & 15;
    const int ty = tid >> 4;

    const int a_row0 = tid >> 2;         // 0..63
    const int a_col4 = (tid & 3) * 4;    // 0,4,8,12
    const int b_row0 = tid >> 5;         // 0..7
    const int b_col4 = (tid & 31) * 4;   // 0..124

    for (int k0 = 0; k0 < K; k0 += BK) {
        // Load A tile (transposed into smem)
        #pragma unroll
        for (int half = 0; half < 2; half++) {
            int r = a_row0 + half * 64;
            float4 v = *reinterpret_cast<const float4*>(&A[(size_t)r * lda + k0 + a_col4]);
            As[a_col4 + 0][r] = v.x;
            As[a_col4 + 1][r] = v.y;
            As[a_col4 + 2][r] = v.z;
            As[a_col4 + 3][r] = v.w;
        }
        // Load B tile
        #pragma unroll
        for (int half = 0; half < 2; half++) {
            int r = b_row0 + half * 8;
            float4 v = *reinterpret_cast<const float4*>(&Bmat[(size_t)(k0 + r) * ldb + b_col4]);
            *reinterpret_cast<float4*>(&Bs[r][b_col4]) = v;
        }
        __syncthreads();

        #pragma unroll
        for (int k = 0; k < BK; k++) {
            float a[TM], b[TN];
            *reinterpret_cast<float4*>(&a[0]) = *reinterpret_cast<const float4*>(&As[k][ty * TM]);
            *reinterpret_cast<float4*>(&a[4]) = *reinterpret_cast<const float4*>(&As[k][ty * TM + 4]);
            *reinterpret_cast<float4*>(&b[0]) = *reinterpret_cast<const float4*>(&Bs[k][tx * TN]);
            *reinterpret_cast<float4*>(&b[4]) = *reinterpret_cast<const float4*>(&Bs[k][tx * TN + 4]);
            #pragma unroll
            for (int m = 0; m < TM; m++)
                #pragma unroll
                for (int n = 0; n < TN; n++)
                    acc[m][n] = fmaf(a[m], b[n], acc[m][n]);
        }
        __syncthreads();
    }
}

// ---------------- Kernel: init state ----------------
__global__ void init_kernel(const float* __restrict__ eps0, const float* __restrict__ sigma0)
{
    size_t i = (size_t)blockIdx.x * blockDim.x + threadIdx.x;
    if (i == 0) g_sum = 0.0;
    if (i < (size_t)B_DIM * Z_DIM) {
        g_z[i] = sigma0[0] * eps0[i];
        g_logw[i] = 0.0f;
    }
}

// ---------------- Kernel: ctx projection (once) ----------------
// g_ctxproj = ctx[B,512] @ W1[128:640, :] + b1
__global__ void __launch_bounds__(NT) ctxproj_kernel(
    const float* __restrict__ ctx, const float* __restrict__ W1, const float* __restrict__ b1)
{
    __shared__ float As[BK][BM];
    __shared__ float Bs[BK][BN];
    float acc[TM][TN] = {};

    const int blockCol = blockIdx.x;
    const int blockRow = blockIdx.y;
    const float* A = ctx + (size_t)blockRow * BM * H_DIM;
    const float* Bm = W1 + (size_t)Z_DIM * HID_DIM + blockCol * BN;

    gemm_128x128(A, H_DIM, Bm, HID_DIM, H_DIM, acc, As, Bs);

    const int tx = threadIdx.x & 15;
    const int ty = threadIdx.x >> 4;
    const int colbase = blockCol * BN + tx * TN;
    const int rowbase = blockRow * BM + ty * TM;

    float bv[TN];
    *reinterpret_cast<float4*>(&bv[0]) = *reinterpret_cast<const float4*>(&b1[colbase]);
    *reinterpret_cast<float4*>(&bv[4]) = *reinterpret_cast<const float4*>(&b1[colbase + 4]);

    #pragma unroll
    for (int m = 0; m < TM; m++) {
        size_t base = (size_t)(rowbase + m) * HID_DIM + colbase;
        float4 o0, o1;
        o0.x = acc[m][0] + bv[0]; o0.y = acc[m][1] + bv[1];
        o0.z = acc[m][2] + bv[2]; o0.w = acc[m][3] + bv[3];
        o1.x = acc[m][4] + bv[4]; o1.y = acc[m][5] + bv[5];
        o1.z = acc[m][6] + bv[6]; o1.w = acc[m][7] + bv[7];
        *reinterpret_cast<float4*>(&g_ctxproj[base])     = o0;
        *reinterpret_cast<float4*>(&g_ctxproj[base + 4]) = o1;
    }
}

// ---------------- Kernel: hidden = relu(z @ W1[:128,:] + ctxproj + te[t]) ----------------
__global__ void __launch_bounds__(NT) hidden_kernel(
    const float* __restrict__ W1, const float* __restrict__ temb, int t)
{
    __shared__ float As[BK][BM];
    __shared__ float Bs[BK][BN];
    float acc[TM][TN] = {};

    const int blockCol = blockIdx.x;
    const int blockRow = blockIdx.y;
    const float* A = g_z + (size_t)blockRow * BM * Z_DIM;
    const float* Bm = W1 + blockCol * BN;

    gemm_128x128(A, Z_DIM, Bm, HID_DIM, Z_DIM, acc, As, Bs);

    const int tx = threadIdx.x & 15;
    const int ty = threadIdx.x >> 4;
    const int colbase = blockCol * BN + tx * TN;
    const int rowbase = blockRow * BM + ty * TM;

    float te[TN];
    *reinterpret_cast<float4*>(&te[0]) = *reinterpret_cast<const float4*>(&temb[(size_t)t * HID_DIM + colbase]);
    *reinterpret_cast<float4*>(&te[4]) = *reinterpret_cast<const float4*>(&temb[(size_t)t * HID_DIM + colbase + 4]);

    #pragma unroll
    for (int m = 0; m < TM; m++) {
        size_t base = (size_t)(rowbase + m) * HID_DIM + colbase;
        float4 c0 = *reinterpret_cast<const float4*>(&g_ctxproj[base]);
        float4 c1 = *reinterpret_cast<const float4*>(&g_ctxproj[base + 4]);
        float v[TN];
        v[0] = acc[m][0] + c0.x + te[0];
        v[1] = acc[m][1] + c0.y + te[1];
        v[2] = acc[m][2] + c0.z + te[2];
        v[3] = acc[m][3] + c0.w + te[3];
        v[4] = acc[m][4] + c1.x + te[4];
        v[5] = acc[m][5] + c1.y + te[5];
        v[6] = acc[m][6] + c1.z + te[6];
        v[7] = acc[m][7] + c1.w + te[7];
        float4 o0, o1;
        o0.x = fmaxf(v[0], 0.f); o0.y = fmaxf(v[1], 0.f);
        o0.z = fmaxf(v[2], 0.f); o0.w = fmaxf(v[3], 0.f);
        o1.x = fmaxf(v[4], 0.f); o1.y = fmaxf(v[5], 0.f);
        o1.z = fmaxf(v[6], 0.f); o1.w = fmaxf(v[7], 0.f);
        *reinterpret_cast<float4*>(&g_h[base])     = o0;
        *reinterpret_cast<float4*>(&g_h[base + 4]) = o1;
    }
}

// ---------------- Kernel: u = h @ W2 + b2, then z/logw update ----------------
__global__ void __launch_bounds__(NT) update_kernel(
    const float* __restrict__ W2, const float* __restrict__ b2,
    const float* __restrict__ eps, const float* __restrict__ beta,
    const float* __restrict__ sigma0, int t)
{
    __shared__ float As[BK][BM];
    __shared__ float Bs[BK][BN];
    float acc[TM][TN] = {};

    const int blockCol = blockIdx.x; // always 0 (N = 128 = BN)
    const int blockRow = blockIdx.y;
    const float* A = g_h + (size_t)blockRow * BM * HID_DIM;
    const float* Bm = W2 + blockCol * BN;

    gemm_128x128(A, HID_DIM, Bm, Z_DIM, HID_DIM, acc, As, Bs);

    const int tx = threadIdx.x & 15;
    const int ty = threadIdx.x >> 4;
    const int colbase = blockCol * BN + tx * TN;
    const int rowbase = blockRow * BM + ty * TM;

    const float dt = 1.0f / T_STEPS;
    const float beta_f = beta[t];
    const float beta_b = beta[(t + T_STEPS - 1) % T_STEPS];
    const float s0 = sigma0[0];
    const float sig_f = sqrtf(2.0f * beta_f * dt) * s0;
    const float sig_b = sqrtf(2.0f * beta_b * dt) * s0;
    const float logdiff = logf(sig_f) - logf(sig_b);
    const float inv_sf = 1.0f / sig_f;
    const float inv_sb = 1.0f / sig_b;

    float bv[TN];
    *reinterpret_cast<float4*>(&bv[0]) = *reinterpret_cast<const float4*>(&b2[colbase]);
    *reinterpret_cast<float4*>(&bv[4]) = *reinterpret_cast<const float4*>(&b2[colbase + 4]);

    const float* eps_t = eps + (size_t)t * B_DIM * Z_DIM;

    #pragma unroll
    for (int m = 0; m < TM; m++) {
        size_t base = (size_t)(rowbase + m) * Z_DIM + colbase;
        float zp[TN], ev[TN], lw[TN];
        *reinterpret_cast<float4*>(&zp[0]) = *reinterpret_cast<const float4*>(&g_z[base]);
        *reinterpret_cast<float4*>(&zp[4]) = *reinterpret_cast<const float4*>(&g_z[base + 4]);
        *reinterpret_cast<float4*>(&ev[0]) = *reinterpret_cast<const float4*>(&eps_t[base]);
        *reinterpret_cast<float4*>(&ev[4]) = *reinterpret_cast<const float4*>(&eps_t[base + 4]);
        *reinterpret_cast<float4*>(&lw[0]) = *reinterpret_cast<const float4*>(&g_logw[base]);
        *reinterpret_cast<float4*>(&lw[4]) = *reinterpret_cast<const float4*>(&g_logw[base + 4]);

        float zn[TN];
        #pragma unroll
        for (int n = 0; n < TN; n++) {
            float u = acc[m][n] + bv[n];
            float mu_f = zp[n] + (beta_f * zp[n] + u) * dt;
            float z_next = mu_f + sig_f * ev[n];
            float mu_b = z_next - beta_b * z_next * dt;
            float a1 = (zp[n] - mu_b) * inv_sb;
            float a2 = (z_next - mu_f) * inv_sf;
            lw[n] += 0.5f * (a2 * a2 - a1 * a1) + logdiff;
            zn[n] = z_next;
        }
        *reinterpret_cast<float4*>(&g_z[base])        = *reinterpret_cast<float4*>(&zn[0]);
        *reinterpret_cast<float4*>(&g_z[base + 4])    = *reinterpret_cast<float4*>(&zn[4]);
        *reinterpret_cast<float4*>(&g_logw[base])     = *reinterpret_cast<float4*>(&lw[0]);
        *reinterpret_cast<float4*>(&g_logw[base + 4]) = *reinterpret_cast<float4*>(&lw[4]);
    }
}

// ---------------- Kernel: terminal correction + global reduction ----------------
__global__ void finalize_reduce(
    const float* __restrict__ eps0, const float* __restrict__ sigma0,
    const float* __restrict__ target_mu)
{
    const float s0 = sigma0[0];
    const float lg = logf(s0);
    double local = 0.0;
    const size_t N = (size_t)B_DIM * Z_DIM;
    for (size_t i = (size_t)blockIdx.x * blockDim.x + threadIdx.x; i < N;
         i += (size_t)gridDim.x * blockDim.x) {
        float zT = g_z[i];
        float d = zT - target_mu[i];
        float z0 = s0 * eps0[i];
        float a = z0 / s0;
        float v = g_logw[i] - 0.5f * d * d + 0.5f * a * a + lg;
        local += (double)v;
    }
    __shared__ double sd[256];
    sd[threadIdx.x] = local;
    __syncthreads();
    for (int s = 128; s > 0; s >>= 1) {
        if (threadIdx.x < s) sd[threadIdx.x] += sd[threadIdx.x + s];
        __syncthreads();
    }
    if (threadIdx.x == 0) atomicAdd(&g_sum, sd[0]);
}

__global__ void write_out(float* __restrict__ out)
{
    out[0] = (float)(g_sum / (double)B_DIM);
}

// ---------------- Host launcher ----------------
extern "C" void kernel_launch(void* const* d_in, const int* in_sizes, int n_in,
                              void* d_out, int out_size)
{
    (void)in_sizes; (void)n_in; (void)out_size;
    const float* ctx    = (const float*)d_in[0];
    const float* eps0   = (const float*)d_in[1];
    const float* eps    = (const float*)d_in[2];
    const float* beta   = (const float*)d_in[3];
    const float* sigma0 = (const float*)d_in[4];
    const float* W1     = (const float*)d_in[5];
    const float* b1     = (const float*)d_in[6];
    const float* W2     = (const float*)d_in[7];
    const float* b2     = (const float*)d_in[8];
    const float* temb   = (const float*)d_in[9];
    const float* tmu    = (const float*)d_in[10];
    float* out = (float*)d_out;

    init_kernel<<<(B_DIM * Z_DIM + 255) / 256, 256>>>(eps0, sigma0);
    ctxproj_kernel<<<dim3(HID_DIM / BN, B_DIM / BM), NT>>>(ctx, W1, b1);
    for (int t = 0; t < T_STEPS; t++) {
        hidden_kernel<<<dim3(HID_DIM / BN, B_DIM / BM), NT>>>(W1, temb, t);
        update_kernel<<<dim3(Z_DIM / BN, B_DIM / BM), NT>>>(W2, b2, eps, beta, sigma0, t);
    }
    finalize_reduce<<<1024, 256>>>(eps0, sigma0, tmu);
    write_out<<<1, 1>>>(out);
}

// round 5
// speedup vs baseline: 2.1478x; 2.1478x over previous
#include <cuda_runtime.h>
#include <cstdint>
#include <math.h>

#define B_DIM  16384
#define ZD     128
#define HD     512
#define TSTEPS 32

// ---------------- device global scratch ----------------
__device__ __align__(16) float g_W1a[ZD * HD];              // W1[0:128,:]  (tf32-rounded)
__device__ __align__(16) float g_W1c[HD * HD];              // W1[128:640,:] (tf32-rounded)
__device__ __align__(16) float g_W2r[HD * ZD];              // W2 (tf32-rounded)
__device__ __align__(16) float g_ctxr[(size_t)B_DIM * HD];  // ctx (tf32-rounded)
__device__ __align__(16) float g_ctxp[(size_t)B_DIM * HD];  // ctx @ W1c + b1
__device__ __align__(16) float g_h[(size_t)B_DIM * HD];     // hidden (tf32-rounded)
__device__ __align__(16) float g_z[(size_t)B_DIM * ZD];     // state z (tf32-rounded)
__device__ __align__(16) float g_logw[(size_t)B_DIM * ZD];  // log-weights
__device__ double g_sum;

// ---------------- helpers ----------------
__device__ __forceinline__ float rna(float x) {
    float r; asm("cvt.rna.tf32.f32 %0, %1;" : "=f"(r) : "f"(x)); return r;
}
__device__ __forceinline__ uint32_t sptr(const void* p) {
    return (uint32_t)__cvta_generic_to_shared(p);
}
__device__ __forceinline__ void cp16(uint32_t d, const float* s) {
    asm volatile("cp.async.cg.shared.global [%0], [%1], 16;" :: "r"(d), "l"(s));
}
#define CP_COMMIT() asm volatile("cp.async.commit_group;" ::: "memory")

// ---------------- tiled tf32 mma.sync GEMM core ----------------
// block tile 128x128, BK=16, 8 warps (4x2), warp tile 32x64 (2 m16 x 8 n8)
#define ASTR 20    // (20r+k)%32: r-groups {0,20,8,28,16,4,24,12}+k -> conflict-free frag loads
#define BSTR 136   // (8k+n)%32 distinct -> conflict-free

struct SmemT {
    float As[2][128][ASTR];  // 20480 B
    float Bs[2][16][BSTR];   // 17408 B
};

__device__ __forceinline__ void gemm_core(
    SmemT* s, const float* __restrict__ A, int lda,
    const float* __restrict__ Bm, int ldb, int K, float acc[2][8][4])
{
    const int tid = threadIdx.x;
    const int lane = tid & 31;
    const int w = tid >> 5, wm = w >> 1, wn = w & 1;
    const int nch = K / 16;

    // prefetch chunk 0
    #pragma unroll
    for (int i = 0; i < 2; i++) {
        int lin = tid + i * 256;
        int r = lin >> 2, kq = (lin & 3) * 4;
        cp16(sptr(&s->As[0][r][kq]), A + (size_t)r * lda + kq);
    }
    #pragma unroll
    for (int i = 0; i < 2; i++) {
        int lin = tid + i * 256;
        int kr = lin >> 5, nq = (lin & 31) * 4;
        cp16(sptr(&s->Bs[0][kr][nq]), Bm + (size_t)kr * ldb + nq);
    }
    CP_COMMIT();

    for (int c = 0; c < nch; c++) {
        const int buf = c & 1;
        if (c + 1 < nch) {
            const int k0 = (c + 1) * 16;
            #pragma unroll
            for (int i = 0; i < 2; i++) {
                int lin = tid + i * 256;
                int r = lin >> 2, kq = (lin & 3) * 4;
                cp16(sptr(&s->As[buf ^ 1][r][kq]), A + (size_t)r * lda + k0 + kq);
            }
            #pragma unroll
            for (int i = 0; i < 2; i++) {
                int lin = tid + i * 256;
                int kr = lin >> 5, nq = (lin & 31) * 4;
                cp16(sptr(&s->Bs[buf ^ 1][kr][nq]), Bm + (size_t)(k0 + kr) * ldb + nq);
            }
            CP_COMMIT();
            asm volatile("cp.async.wait_group 1;" ::: "memory");
        } else {
            asm volatile("cp.async.wait_group 0;" ::: "memory");
        }
        __syncthreads();

        #pragma unroll
        for (int kk = 0; kk < 16; kk += 8) {
            uint32_t af[2][4], bf[8][2];
            const int kb = kk + (lane & 3);
            #pragma unroll
            for (int mt = 0; mt < 2; mt++) {
                int r = wm * 32 + mt * 16 + (lane >> 2);
                af[mt][0] = __float_as_uint(s->As[buf][r][kb]);
                af[mt][1] = __float_as_uint(s->As[buf][r + 8][kb]);
                af[mt][2] = __float_as_uint(s->As[buf][r][kb + 4]);
                af[mt][3] = __float_as_uint(s->As[buf][r + 8][kb + 4]);
            }
            #pragma unroll
            for (int nt = 0; nt < 8; nt++) {
                int nn = wn * 64 + nt * 8 + (lane >> 2);
                bf[nt][0] = __float_as_uint(s->Bs[buf][kb][nn]);
                bf[nt][1] = __float_as_uint(s->Bs[buf][kb + 4][nn]);
            }
            #pragma unroll
            for (int mt = 0; mt < 2; mt++)
                #pragma unroll
                for (int nt = 0; nt < 8; nt++)
                    asm volatile(
                        "mma.sync.aligned.m16n8k8.row.col.f32.tf32.tf32.f32 "
                        "{%0,%1,%2,%3}, {%4,%5,%6,%7}, {%8,%9}, {%0,%1,%2,%3};"
                        : "+f"(acc[mt][nt][0]), "+f"(acc[mt][nt][1]),
                          "+f"(acc[mt][nt][2]), "+f"(acc[mt][nt][3])
                        : "r"(af[mt][0]), "r"(af[mt][1]), "r"(af[mt][2]), "r"(af[mt][3]),
                          "r"(bf[nt][0]), "r"(bf[nt][1]));
        }
        __syncthreads();
    }
}

// fragment (row, col) helpers: row = wm*32+mt*16+(lane>>2)(+8), col = wn*64+nt*8+2*(lane&3)(+1)

// ---------------- prep kernels ----------------
__global__ void prep_w(const float* __restrict__ W1, const float* __restrict__ W2)
{
    const int NW1 = 640 * 512, NW2 = 512 * 128;
    for (int i = blockIdx.x * blockDim.x + threadIdx.x; i < NW1 + NW2;
         i += gridDim.x * blockDim.x) {
        if (i < 65536)          g_W1a[i] = rna(W1[i]);
        else if (i < NW1)       g_W1c[i - 65536] = rna(W1[i]);
        else                    g_W2r[i - NW1] = rna(W2[i - NW1]);
    }
}
__global__ void prep_ctx(const float* __restrict__ ctx)
{
    const size_t N = (size_t)B_DIM * HD;
    for (size_t i = (size_t)blockIdx.x * blockDim.x + threadIdx.x; i < N;
         i += (size_t)gridDim.x * blockDim.x)
        g_ctxr[i] = rna(ctx[i]);
}
__global__ void init_state(const float* __restrict__ eps0, const float* __restrict__ sigma0)
{
    const float s0 = sigma0[0];
    const size_t N = (size_t)B_DIM * ZD;
    size_t i0 = (size_t)blockIdx.x * blockDim.x + threadIdx.x;
    if (i0 == 0) g_sum = 0.0;
    for (size_t i = i0; i < N; i += (size_t)gridDim.x * blockDim.x) {
        g_z[i] = rna(s0 * eps0[i]);
        g_logw[i] = 0.0f;
    }
}

// ---------------- ctxproj: g_ctxp = ctxr @ W1c + b1 ----------------
__global__ void __launch_bounds__(256, 2) ctxproj_kernel(const float* __restrict__ b1)
{
    __shared__ SmemT s;
    float acc[2][8][4] = {};
    const int brow = blockIdx.y, bcol = blockIdx.x;
    gemm_core(&s, g_ctxr + (size_t)brow * 128 * HD, HD, g_W1c + bcol * 128, HD, HD, acc);

    const int lane = threadIdx.x & 31;
    const int w = threadIdx.x >> 5, wm = w >> 1, wn = w & 1;
    #pragma unroll
    for (int mt = 0; mt < 2; mt++) {
        #pragma unroll
        for (int nt = 0; nt < 8; nt++) {
            int r = brow * 128 + wm * 32 + mt * 16 + (lane >> 2);
            int c = bcol * 128 + wn * 64 + nt * 8 + 2 * (lane & 3);
            float2 bv = *reinterpret_cast<const float2*>(&b1[c]);
            float2 o0 = { acc[mt][nt][0] + bv.x, acc[mt][nt][1] + bv.y };
            float2 o1 = { acc[mt][nt][2] + bv.x, acc[mt][nt][3] + bv.y };
            *reinterpret_cast<float2*>(&g_ctxp[(size_t)r * HD + c]) = o0;
            *reinterpret_cast<float2*>(&g_ctxp[(size_t)(r + 8) * HD + c]) = o1;
        }
    }
}

// ---------------- hidden: g_h = rna(relu(z @ W1a + ctxp + te_t)) ----------------
__global__ void __launch_bounds__(256, 2) hidden_kernel(const float* __restrict__ temb, int t)
{
    __shared__ SmemT s;
    float acc[2][8][4] = {};
    const int brow = blockIdx.y, bcol = blockIdx.x;
    gemm_core(&s, g_z + (size_t)brow * 128 * ZD, ZD, g_W1a + bcol * 128, HD, ZD, acc);

    const int lane = threadIdx.x & 31;
    const int w = threadIdx.x >> 5, wm = w >> 1, wn = w & 1;
    #pragma unroll
    for (int mt = 0; mt < 2; mt++) {
        #pragma unroll
        for (int nt = 0; nt < 8; nt++) {
            int r = brow * 128 + wm * 32 + mt * 16 + (lane >> 2);
            int c = bcol * 128 + wn * 64 + nt * 8 + 2 * (lane & 3);
            float2 te = *reinterpret_cast<const float2*>(&temb[(size_t)t * HD + c]);
            float2 cp0 = *reinterpret_cast<const float2*>(&g_ctxp[(size_t)r * HD + c]);
            float2 cp1 = *reinterpret_cast<const float2*>(&g_ctxp[(size_t)(r + 8) * HD + c]);
            float2 o0, o1;
            o0.x = rna(fmaxf(acc[mt][nt][0] + cp0.x + te.x, 0.f));
            o0.y = rna(fmaxf(acc[mt][nt][1] + cp0.y + te.y, 0.f));
            o1.x = rna(fmaxf(acc[mt][nt][2] + cp1.x + te.x, 0.f));
            o1.y = rna(fmaxf(acc[mt][nt][3] + cp1.y + te.y, 0.f));
            *reinterpret_cast<float2*>(&g_h[(size_t)r * HD + c]) = o0;
            *reinterpret_cast<float2*>(&g_h[(size_t)(r + 8) * HD + c]) = o1;
        }
    }
}

// ---------------- update: u = h @ W2 + b2; z/logw step ----------------
__global__ void __launch_bounds__(256, 2) update_kernel(
    const float* __restrict__ eps, const float* __restrict__ beta,
    const float* __restrict__ sigma0, const float* __restrict__ b2, int t)
{
    __shared__ SmemT s;
    float acc[2][8][4] = {};
    const int brow = blockIdx.y;
    gemm_core(&s, g_h + (size_t)brow * 128 * HD, HD, g_W2r, ZD, HD, acc);

    const int lane = threadIdx.x & 31;
    const int w = threadIdx.x >> 5, wm = w >> 1, wn = w & 1;

    const float dt = 1.0f / TSTEPS;
    const float beta_f = beta[t];
    const float beta_b = beta[(t + TSTEPS - 1) % TSTEPS];
    const float s0 = sigma0[0];
    const float sig_f = sqrtf(2.0f * beta_f * dt) * s0;
    const float sig_b = sqrtf(2.0f * beta_b * dt) * s0;
    const float inv_sb = 1.0f / sig_b;
    const float logdiff = logf(sig_f) - logf(sig_b);
    const float* eps_t = eps + (size_t)t * B_DIM * ZD;

    #pragma unroll
    for (int mt = 0; mt < 2; mt++) {
        #pragma unroll
        for (int nt = 0; nt < 8; nt++) {
            int r = brow * 128 + wm * 32 + mt * 16 + (lane >> 2);
            int c = wn * 64 + nt * 8 + 2 * (lane & 3);
            float2 bv = *reinterpret_cast<const float2*>(&b2[c]);
            #pragma unroll
            for (int half = 0; half < 2; half++) {
                int rr = r + half * 8;
                size_t base = (size_t)rr * ZD + c;
                float2 zp = *reinterpret_cast<const float2*>(&g_z[base]);
                float2 ev = *reinterpret_cast<const float2*>(&eps_t[base]);
                float2 lw = *reinterpret_cast<const float2*>(&g_logw[base]);
                float u0 = acc[mt][nt][half * 2 + 0] + bv.x;
                float u1 = acc[mt][nt][half * 2 + 1] + bv.y;
                float mu0 = zp.x + (beta_f * zp.x + u0) * dt;
                float mu1 = zp.y + (beta_f * zp.y + u1) * dt;
                float zn0 = fmaf(sig_f, ev.x, mu0);
                float zn1 = fmaf(sig_f, ev.y, mu1);
                float mb0 = zn0 - beta_b * zn0 * dt;
                float mb1 = zn1 - beta_b * zn1 * dt;
                float a10 = (zp.x - mb0) * inv_sb;
                float a11 = (zp.y - mb1) * inv_sb;
                lw.x += 0.5f * (ev.x * ev.x - a10 * a10) + logdiff;
                lw.y += 0.5f * (ev.y * ev.y - a11 * a11) + logdiff;
                float2 zo = { rna(zn0), rna(zn1) };
                *reinterpret_cast<float2*>(&g_z[base]) = zo;
                *reinterpret_cast<float2*>(&g_logw[base]) = lw;
            }
        }
    }
}

// ---------------- finalize ----------------
__global__ void finalize_reduce(
    const float* __restrict__ eps0, const float* __restrict__ sigma0,
    const float* __restrict__ target_mu)
{
    const float s0 = sigma0[0];
    const float lg = logf(s0);
    double local = 0.0;
    const size_t N = (size_t)B_DIM * ZD;
    for (size_t i = (size_t)blockIdx.x * blockDim.x + threadIdx.x; i < N;
         i += (size_t)gridDim.x * blockDim.x) {
        float zT = g_z[i];
        float d = zT - target_mu[i];
        float a = eps0[i];
        local += (double)(g_logw[i] - 0.5f * d * d + 0.5f * a * a + lg);
    }
    __shared__ double sd[256];
    sd[threadIdx.x] = local;
    __syncthreads();
    for (int st = 128; st > 0; st >>= 1) {
        if (threadIdx.x < st) sd[threadIdx.x] += sd[threadIdx.x + st];
        __syncthreads();
    }
    if (threadIdx.x == 0) atomicAdd(&g_sum, sd[0]);
}

__global__ void write_out(float* __restrict__ out)
{
    out[0] = (float)(g_sum / (double)B_DIM);
}

// ---------------- host launcher ----------------
extern "C" void kernel_launch(void* const* d_in, const int* in_sizes, int n_in,
                              void* d_out, int out_size)
{
    (void)in_sizes; (void)n_in; (void)out_size;
    const float* ctx    = (const float*)d_in[0];
    const float* eps0   = (const float*)d_in[1];
    const float* eps    = (const float*)d_in[2];
    const float* beta   = (const float*)d_in[3];
    const float* sigma0 = (const float*)d_in[4];
    const float* W1     = (const float*)d_in[5];
    const float* b1     = (const float*)d_in[6];
    const float* W2     = (const float*)d_in[7];
    const float* b2     = (const float*)d_in[8];
    const float* temb   = (const float*)d_in[9];
    const float* tmu    = (const float*)d_in[10];
    float* out = (float*)d_out;

    prep_w<<<512, 256>>>(W1, W2);
    prep_ctx<<<2048, 256>>>(ctx);
    init_state<<<2048, 256>>>(eps0, sigma0);
    ctxproj_kernel<<<dim3(4, 128), 256>>>(b1);
    for (int t = 0; t < TSTEPS; t++) {
        hidden_kernel<<<dim3(4, 128), 256>>>(temb, t);
        update_kernel<<<dim3(1, 128), 256>>>(eps, beta, sigma0, b2, t);
    }
    finalize_reduce<<<1024, 256>>>(eps0, sigma0, tmu);
    write_out<<<1, 1>>>(out);
}

// round 6
// speedup vs baseline: 3.6865x; 1.7164x over previous
#include <cuda_runtime.h>
#include <cstdint>
#include <math.h>

#define B_DIM  16384
#define ZD     128
#define HD     512
#define TSTEPS 32

// ---------------- device global scratch ----------------
__device__ __align__(16) float g_W1a[ZD * HD];              // W1[0:128,:]  (tf32-rounded)
__device__ __align__(16) float g_W1c[HD * HD];              // W1[128:640,:] (tf32-rounded)
__device__ __align__(16) float g_W2r[HD * ZD];              // W2 (tf32-rounded)
__device__ __align__(16) float g_ctxr[(size_t)B_DIM * HD];  // ctx (tf32-rounded)
__device__ __align__(16) float g_ctxp[(size_t)B_DIM * HD];  // ctx @ W1c + b1
__device__ double g_sum;

// ---------------- helpers ----------------
__device__ __forceinline__ float rna(float x) {
    float r; asm("cvt.rna.tf32.f32 %0, %1;" : "=f"(r) : "f"(x)); return r;
}
__device__ __forceinline__ uint32_t sptr(const void* p) {
    return (uint32_t)__cvta_generic_to_shared(p);
}
__device__ __forceinline__ void cp16(uint32_t d, const float* s) {
    asm volatile("cp.async.cg.shared.global [%0], [%1], 16;" :: "r"(d), "l"(s));
}
#define CP_COMMIT() asm volatile("cp.async.commit_group;" ::: "memory")
#define MMA_TF32(acc, af, bf) \
    asm volatile("mma.sync.aligned.m16n8k8.row.col.f32.tf32.tf32.f32 " \
        "{%0,%1,%2,%3}, {%4,%5,%6,%7}, {%8,%9}, {%0,%1,%2,%3};" \
        : "+f"((acc)[0]), "+f"((acc)[1]), "+f"((acc)[2]), "+f"((acc)[3]) \
        : "r"((af)[0]), "r"((af)[1]), "r"((af)[2]), "r"((af)[3]), \
          "r"((bf)[0]), "r"((bf)[1]))

// ================= ctxproj GEMM (proven R4 core) =================
#define ASTR 20
#define BSTR 136

struct SmemT {
    float As[2][128][ASTR];
    float Bs[2][16][BSTR];
};

__device__ __forceinline__ void gemm_core(
    SmemT* s, const float* __restrict__ A, int lda,
    const float* __restrict__ Bm, int ldb, int K, float acc[2][8][4])
{
    const int tid = threadIdx.x;
    const int lane = tid & 31;
    const int w = tid >> 5, wm = w >> 1, wn = w & 1;
    const int nch = K / 16;

    #pragma unroll
    for (int i = 0; i < 2; i++) {
        int lin = tid + i * 256;
        int r = lin >> 2, kq = (lin & 3) * 4;
        cp16(sptr(&s->As[0][r][kq]), A + (size_t)r * lda + kq);
    }
    #pragma unroll
    for (int i = 0; i < 2; i++) {
        int lin = tid + i * 256;
        int kr = lin >> 5, nq = (lin & 31) * 4;
        cp16(sptr(&s->Bs[0][kr][nq]), Bm + (size_t)kr * ldb + nq);
    }
    CP_COMMIT();

    for (int c = 0; c < nch; c++) {
        const int buf = c & 1;
        if (c + 1 < nch) {
            const int k0 = (c + 1) * 16;
            #pragma unroll
            for (int i = 0; i < 2; i++) {
                int lin = tid + i * 256;
                int r = lin >> 2, kq = (lin & 3) * 4;
                cp16(sptr(&s->As[buf ^ 1][r][kq]), A + (size_t)r * lda + k0 + kq);
            }
            #pragma unroll
            for (int i = 0; i < 2; i++) {
                int lin = tid + i * 256;
                int kr = lin >> 5, nq = (lin & 31) * 4;
                cp16(sptr(&s->Bs[buf ^ 1][kr][nq]), Bm + (size_t)(k0 + kr) * ldb + nq);
            }
            CP_COMMIT();
            asm volatile("cp.async.wait_group 1;" ::: "memory");
        } else {
            asm volatile("cp.async.wait_group 0;" ::: "memory");
        }
        __syncthreads();

        #pragma unroll
        for (int kk = 0; kk < 16; kk += 8) {
            uint32_t af[2][4], bf[8][2];
            const int kb = kk + (lane & 3);
            #pragma unroll
            for (int mt = 0; mt < 2; mt++) {
                int r = wm * 32 + mt * 16 + (lane >> 2);
                af[mt][0] = __float_as_uint(s->As[buf][r][kb]);
                af[mt][1] = __float_as_uint(s->As[buf][r + 8][kb]);
                af[mt][2] = __float_as_uint(s->As[buf][r][kb + 4]);
                af[mt][3] = __float_as_uint(s->As[buf][r + 8][kb + 4]);
            }
            #pragma unroll
            for (int nt = 0; nt < 8; nt++) {
                int nn = wn * 64 + nt * 8 + (lane >> 2);
                bf[nt][0] = __float_as_uint(s->Bs[buf][kb][nn]);
                bf[nt][1] = __float_as_uint(s->Bs[buf][kb + 4][nn]);
            }
            #pragma unroll
            for (int mt = 0; mt < 2; mt++)
                #pragma unroll
                for (int nt = 0; nt < 8; nt++)
                    MMA_TF32(acc[mt][nt], af[mt], bf[nt]);
        }
        __syncthreads();
    }
}

__global__ void __launch_bounds__(256, 2) ctxproj_kernel(const float* __restrict__ b1)
{
    __shared__ SmemT s;
    float acc[2][8][4] = {};
    const int brow = blockIdx.y, bcol = blockIdx.x;
    gemm_core(&s, g_ctxr + (size_t)brow * 128 * HD, HD, g_W1c + bcol * 128, HD, HD, acc);

    const int lane = threadIdx.x & 31;
    const int w = threadIdx.x >> 5, wm = w >> 1, wn = w & 1;
    #pragma unroll
    for (int mt = 0; mt < 2; mt++) {
        #pragma unroll
        for (int nt = 0; nt < 8; nt++) {
            int r = brow * 128 + wm * 32 + mt * 16 + (lane >> 2);
            int c = bcol * 128 + wn * 64 + nt * 8 + 2 * (lane & 3);
            float2 bv = *reinterpret_cast<const float2*>(&b1[c]);
            float2 o0 = { acc[mt][nt][0] + bv.x, acc[mt][nt][1] + bv.y };
            float2 o1 = { acc[mt][nt][2] + bv.x, acc[mt][nt][3] + bv.y };
            *reinterpret_cast<float2*>(&g_ctxp[(size_t)r * HD + c]) = o0;
            *reinterpret_cast<float2*>(&g_ctxp[(size_t)(r + 8) * HD + c]) = o1;
        }
    }
}

// ================= persistent fused step kernel =================
// A tiles (z, h): [4 chunks][128 rows][36]  (stride 36: (4r+k)%32 distinct)
// B tile (weights): [2 bufs][32 k][136]
#define AST2 36

struct PSmem {
    float z[4][128][AST2];   // 73728 B
    float h[4][128][AST2];   // 73728 B
    float wb[2][32][136];    // 34816 B
};
#define PSMEM_SZ ((int)sizeof(PSmem))

extern __shared__ char dynsm[];

// weight slice si (0..31): chunk c = si>>3, phase = (si>>2)&1 (0:W1a, 1:W2), kc = si&3
__device__ __forceinline__ void load_slice(PSmem* s, int buf, int si, int tid)
{
    const int c = si >> 3, ph = (si >> 2) & 1, kc = si & 3;
    const float* src;
    int ld;
    if (!ph) { src = g_W1a + (size_t)(kc * 32) * HD + c * 128; ld = HD; }
    else     { src = g_W2r + (size_t)(c * 128 + kc * 32) * ZD; ld = ZD; }
    #pragma unroll
    for (int i = 0; i < 2; i++) {
        int lin = tid + i * 512;
        int kr = lin >> 5, nq = (lin & 31) * 4;
        cp16(sptr(&s->wb[buf][kr][nq]), src + (size_t)kr * ld + nq);
    }
    CP_COMMIT();
}

__device__ __forceinline__ void mma32(float acc[2][4][4],
    const float (&A)[128][AST2], const float (&Bm)[32][136],
    int lane, int wm, int wn)
{
    #pragma unroll
    for (int kk = 0; kk < 32; kk += 8) {
        const int kb = kk + (lane & 3);
        uint32_t af[2][4], bf[4][2];
        #pragma unroll
        for (int mt = 0; mt < 2; mt++) {
            int r = wm * 32 + mt * 16 + (lane >> 2);
            af[mt][0] = __float_as_uint(A[r][kb]);
            af[mt][1] = __float_as_uint(A[r + 8][kb]);
            af[mt][2] = __float_as_uint(A[r][kb + 4]);
            af[mt][3] = __float_as_uint(A[r + 8][kb + 4]);
        }
        #pragma unroll
        for (int nt = 0; nt < 4; nt++) {
            int nn = wn * 32 + nt * 8 + (lane >> 2);
            bf[nt][0] = __float_as_uint(Bm[kb][nn]);
            bf[nt][1] = __float_as_uint(Bm[kb + 4][nn]);
        }
        #pragma unroll
        for (int mt = 0; mt < 2; mt++)
            #pragma unroll
            for (int nt = 0; nt < 4; nt++)
                MMA_TF32(acc[mt][nt], af[mt], bf[nt]);
    }
}

__global__ void __launch_bounds__(512, 1) step_kernel(
    const float* __restrict__ eps0, const float* __restrict__ eps,
    const float* __restrict__ beta, const float* __restrict__ sigma0,
    const float* __restrict__ b2,   const float* __restrict__ temb,
    const float* __restrict__ tmu)
{
    PSmem* s = (PSmem*)dynsm;
    const int tid = threadIdx.x, lane = tid & 31, w = tid >> 5;
    const int wm = w >> 2, wn = w & 3;
    const int grow0 = blockIdx.x * 128;

    const float s0 = sigma0[0];
    const float lg = logf(s0);
    const float dt = 1.0f / TSTEPS;
    double ssum = 0.0;

    // ---- init z in smem + prior-correction term ----
    {
        float local = 0.f;
        #pragma unroll
        for (int i = 0; i < 8; i++) {
            int lin4 = (tid + i * 512) * 4;
            int row = lin4 >> 7, col = lin4 & 127;
            float4 e = *reinterpret_cast<const float4*>(&eps0[(size_t)(grow0 + row) * ZD + col]);
            float* zp = &s->z[col >> 5][row][col & 31];
            zp[0] = rna(s0 * e.x); zp[1] = rna(s0 * e.y);
            zp[2] = rna(s0 * e.z); zp[3] = rna(s0 * e.w);
            local += 0.5f * (e.x * e.x + e.y * e.y + e.z * e.z + e.w * e.w) + 4.f * lg;
        }
        ssum += (double)local;
    }
    load_slice(s, 0, 0, tid);
    __syncthreads();

    int buf = 0;
    for (int t = 0; t < TSTEPS; t++) {
        const float beta_f = __ldg(&beta[t]);
        const float beta_b = __ldg(&beta[(t + TSTEPS - 1) % TSTEPS]);
        const float sig_f = sqrtf(2.0f * beta_f * dt) * s0;
        const float sig_b = sqrtf(2.0f * beta_b * dt) * s0;
        const float inv_sb = 1.0f / sig_b;
        const float logdiff = logf(sig_f) - logf(sig_b);

        float accu[2][4][4] = {};

        for (int c = 0; c < 4; c++) {
            // ---- MMA1: h_acc = z @ W1a[:, c*128:+128] ----
            float acch[2][4][4] = {};
            #pragma unroll
            for (int kc = 0; kc < 4; kc++) {
                int si = c * 8 + kc;
                load_slice(s, buf ^ 1, (si + 1) & 31, tid);
                asm volatile("cp.async.wait_group 1;" ::: "memory");
                __syncthreads();
                mma32(acch, s->z[kc], s->wb[buf], lane, wm, wn);
                __syncthreads();
                buf ^= 1;
            }
            // ---- epilogue1: h = rna(relu(acch + ctxp + te)) -> h smem ----
            #pragma unroll
            for (int mt = 0; mt < 2; mt++) {
                #pragma unroll
                for (int nt = 0; nt < 4; nt++) {
                    int r = wm * 32 + mt * 16 + (lane >> 2);
                    int cc = wn * 32 + nt * 8 + 2 * (lane & 3);
                    int gc = c * 128 + cc;
                    float2 te = *reinterpret_cast<const float2*>(&temb[(size_t)t * HD + gc]);
                    #pragma unroll
                    for (int hf = 0; hf < 2; hf++) {
                        int rr = r + 8 * hf;
                        float2 cp = *reinterpret_cast<const float2*>(
                            &g_ctxp[(size_t)(grow0 + rr) * HD + gc]);
                        float v0 = rna(fmaxf(acch[mt][nt][hf * 2 + 0] + cp.x + te.x, 0.f));
                        float v1 = rna(fmaxf(acch[mt][nt][hf * 2 + 1] + cp.y + te.y, 0.f));
                        float* hp = &s->h[cc >> 5][rr][cc & 31];
                        hp[0] = v0; hp[1] = v1;
                    }
                }
            }
            __syncthreads();
            // ---- MMA2: u_acc += h @ W2[c*128:+128, :] ----
            #pragma unroll
            for (int kc = 0; kc < 4; kc++) {
                int si = c * 8 + 4 + kc;
                load_slice(s, buf ^ 1, (si + 1) & 31, tid);
                asm volatile("cp.async.wait_group 1;" ::: "memory");
                __syncthreads();
                mma32(accu, s->h[kc], s->wb[buf], lane, wm, wn);
                __syncthreads();
                buf ^= 1;
            }
        }

        // ---- update epilogue: z/logw step ----
        const float* eps_t = eps + ((size_t)t * B_DIM + grow0) * ZD;
        float local = 0.f;
        #pragma unroll
        for (int mt = 0; mt < 2; mt++) {
            #pragma unroll
            for (int nt = 0; nt < 4; nt++) {
                int r = wm * 32 + mt * 16 + (lane >> 2);
                int cc = wn * 32 + nt * 8 + 2 * (lane & 3);
                float2 bv = *reinterpret_cast<const float2*>(&b2[cc]);
                #pragma unroll
                for (int hf = 0; hf < 2; hf++) {
                    int rr = r + 8 * hf;
                    float* zp = &s->z[cc >> 5][rr][cc & 31];
                    float2 ev = *reinterpret_cast<const float2*>(&eps_t[(size_t)rr * ZD + cc]);
                    float u0 = accu[mt][nt][hf * 2 + 0] + bv.x;
                    float u1 = accu[mt][nt][hf * 2 + 1] + bv.y;
                    float z0 = zp[0], z1 = zp[1];
                    float mu0 = z0 + (beta_f * z0 + u0) * dt;
                    float mu1 = z1 + (beta_f * z1 + u1) * dt;
                    float zn0 = fmaf(sig_f, ev.x, mu0);
                    float zn1 = fmaf(sig_f, ev.y, mu1);
                    float mb0 = zn0 - beta_b * zn0 * dt;
                    float mb1 = zn1 - beta_b * zn1 * dt;
                    float a10 = (z0 - mb0) * inv_sb;
                    float a11 = (z1 - mb1) * inv_sb;
                    local += 0.5f * (ev.x * ev.x - a10 * a10) + logdiff;
                    local += 0.5f * (ev.y * ev.y - a11 * a11) + logdiff;
                    if (t == TSTEPS - 1) {
                        float2 tm = *reinterpret_cast<const float2*>(
                            &tmu[(size_t)(grow0 + rr) * ZD + cc]);
                        float d0 = zn0 - tm.x, d1 = zn1 - tm.y;
                        local -= 0.5f * (d0 * d0 + d1 * d1);
                    }
                    zp[0] = rna(zn0);
                    zp[1] = rna(zn1);
                }
            }
        }
        ssum += (double)local;
        __syncthreads();
    }

    // ---- reduce ----
    asm volatile("cp.async.wait_group 0;" ::: "memory");
    __syncthreads();
    double* red = reinterpret_cast<double*>(&s->wb[0][0][0]);
    red[tid] = ssum;
    __syncthreads();
    for (int st = 256; st > 0; st >>= 1) {
        if (tid < st) red[tid] += red[tid + st];
        __syncthreads();
    }
    if (tid == 0) atomicAdd(&g_sum, red[0]);
}

// ---------------- prep / finalize ----------------
__global__ void prep_w(const float* __restrict__ W1, const float* __restrict__ W2)
{
    const int NW1 = 640 * 512, NW2 = 512 * 128;
    for (int i = blockIdx.x * blockDim.x + threadIdx.x; i < NW1 + NW2;
         i += gridDim.x * blockDim.x) {
        if (i < 65536)    g_W1a[i] = rna(W1[i]);
        else if (i < NW1) g_W1c[i - 65536] = rna(W1[i]);
        else              g_W2r[i - NW1] = rna(W2[i - NW1]);
    }
}
__global__ void prep_ctx(const float* __restrict__ ctx)
{
    const size_t N = (size_t)B_DIM * HD;
    size_t i0 = (size_t)blockIdx.x * blockDim.x + threadIdx.x;
    if (i0 == 0) g_sum = 0.0;
    for (size_t i = i0; i < N; i += (size_t)gridDim.x * blockDim.x)
        g_ctxr[i] = rna(ctx[i]);
}
__global__ void write_out(float* __restrict__ out)
{
    out[0] = (float)(g_sum / (double)B_DIM);
}

// ---------------- host launcher ----------------
extern "C" void kernel_launch(void* const* d_in, const int* in_sizes, int n_in,
                              void* d_out, int out_size)
{
    (void)in_sizes; (void)n_in; (void)out_size;
    const float* ctx    = (const float*)d_in[0];
    const float* eps0   = (const float*)d_in[1];
    const float* eps    = (const float*)d_in[2];
    const float* beta   = (const float*)d_in[3];
    const float* sigma0 = (const float*)d_in[4];
    const float* W1     = (const float*)d_in[5];
    const float* b1     = (const float*)d_in[6];
    const float* W2     = (const float*)d_in[7];
    const float* b2     = (const float*)d_in[8];
    const float* temb   = (const float*)d_in[9];
    const float* tmu    = (const float*)d_in[10];
    float* out = (float*)d_out;

    cudaFuncSetAttribute(step_kernel, cudaFuncAttributeMaxDynamicSharedMemorySize, PSMEM_SZ);

    prep_w<<<512, 256>>>(W1, W2);
    prep_ctx<<<2048, 256>>>(ctx);
    ctxproj_kernel<<<dim3(4, 128), 256>>>(b1);
    step_kernel<<<128, 512, PSMEM_SZ>>>(eps0, eps, beta, sigma0, b2, temb, tmu);
    write_out<<<1, 1>>>(out);
}

// round 7
// speedup vs baseline: 5.7523x; 1.5604x over previous
#include <cuda_runtime.h>
#include <cstdint>
#include <math.h>

#define B_DIM  16384
#define ZD     128
#define HD     512
#define TSTEPS 32

// ---------------- device global scratch ----------------
__device__ __align__(16) float    g_W1c[HD * HD];               // W1[128:640,:] tf32 (ctxproj)
__device__ __align__(16) float    g_ctxr[(size_t)B_DIM * HD];   // ctx tf32 (ctxproj)
__device__ __align__(16) uint32_t g_ctxpb[(size_t)B_DIM * 256]; // ctxproj, packed bf16x2 pairs
__device__ __align__(16) uint32_t g_Wsl[32 * 2048];             // 32 weight slices, bf16x2 [16q][128n]
__device__ double g_sum;

// ---------------- helpers ----------------
__device__ __forceinline__ float rna(float x) {
    float r; asm("cvt.rna.tf32.f32 %0, %1;" : "=f"(r) : "f"(x)); return r;
}
__device__ __forceinline__ uint32_t packbf(float lo, float hi) {
    uint32_t r; asm("cvt.rn.bf16x2.f32 %0, %1, %2;" : "=r"(r) : "f"(hi), "f"(lo)); return r;
}
__device__ __forceinline__ float bflo(uint32_t u) { return __uint_as_float(u << 16); }
__device__ __forceinline__ float bfhi(uint32_t u) { return __uint_as_float(u & 0xFFFF0000u); }
__device__ __forceinline__ uint32_t sptr(const void* p) {
    return (uint32_t)__cvta_generic_to_shared(p);
}
__device__ __forceinline__ void cp16(uint32_t d, const void* s) {
    asm volatile("cp.async.cg.shared.global [%0], [%1], 16;" :: "r"(d), "l"(s));
}
#define CP_COMMIT() asm volatile("cp.async.commit_group;" ::: "memory")

#define MMA_TF32(acc, af, bf) \
    asm volatile("mma.sync.aligned.m16n8k8.row.col.f32.tf32.tf32.f32 " \
        "{%0,%1,%2,%3}, {%4,%5,%6,%7}, {%8,%9}, {%0,%1,%2,%3};" \
        : "+f"((acc)[0]), "+f"((acc)[1]), "+f"((acc)[2]), "+f"((acc)[3]) \
        : "r"((af)[0]), "r"((af)[1]), "r"((af)[2]), "r"((af)[3]), \
          "r"((bf)[0]), "r"((bf)[1]))

#define MMA_BF16(acc, af, b0, b1) \
    asm volatile("mma.sync.aligned.m16n8k16.row.col.f32.bf16.bf16.f32 " \
        "{%0,%1,%2,%3}, {%4,%5,%6,%7}, {%8,%9}, {%0,%1,%2,%3};" \
        : "+f"((acc)[0]), "+f"((acc)[1]), "+f"((acc)[2]), "+f"((acc)[3]) \
        : "r"((af)[0]), "r"((af)[1]), "r"((af)[2]), "r"((af)[3]), \
          "r"(b0), "r"(b1))

// ================= ctxproj tf32 GEMM (proven core) =================
#define ASTR 20
#define BSTR 136

struct SmemT {
    float As[2][128][ASTR];
    float Bs[2][16][BSTR];
};

__device__ __forceinline__ void gemm_core(
    SmemT* s, const float* __restrict__ A, int lda,
    const float* __restrict__ Bm, int ldb, int K, float acc[2][8][4])
{
    const int tid = threadIdx.x;
    const int lane = tid & 31;
    const int w = tid >> 5, wm = w >> 1, wn = w & 1;
    const int nch = K / 16;

    #pragma unroll
    for (int i = 0; i < 2; i++) {
        int lin = tid + i * 256;
        int r = lin >> 2, kq = (lin & 3) * 4;
        cp16(sptr(&s->As[0][r][kq]), A + (size_t)r * lda + kq);
    }
    #pragma unroll
    for (int i = 0; i < 2; i++) {
        int lin = tid + i * 256;
        int kr = lin >> 5, nq = (lin & 31) * 4;
        cp16(sptr(&s->Bs[0][kr][nq]), Bm + (size_t)kr * ldb + nq);
    }
    CP_COMMIT();

    for (int c = 0; c < nch; c++) {
        const int buf = c & 1;
        if (c + 1 < nch) {
            const int k0 = (c + 1) * 16;
            #pragma unroll
            for (int i = 0; i < 2; i++) {
                int lin = tid + i * 256;
                int r = lin >> 2, kq = (lin & 3) * 4;
                cp16(sptr(&s->As[buf ^ 1][r][kq]), A + (size_t)r * lda + k0 + kq);
            }
            #pragma unroll
            for (int i = 0; i < 2; i++) {
                int lin = tid + i * 256;
                int kr = lin >> 5, nq = (lin & 31) * 4;
                cp16(sptr(&s->Bs[buf ^ 1][kr][nq]), Bm + (size_t)(k0 + kr) * ldb + nq);
            }
            CP_COMMIT();
            asm volatile("cp.async.wait_group 1;" ::: "memory");
        } else {
            asm volatile("cp.async.wait_group 0;" ::: "memory");
        }
        __syncthreads();

        #pragma unroll
        for (int kk = 0; kk < 16; kk += 8) {
            uint32_t af[2][4], bf[8][2];
            const int kb = kk + (lane & 3);
            #pragma unroll
            for (int mt = 0; mt < 2; mt++) {
                int r = wm * 32 + mt * 16 + (lane >> 2);
                af[mt][0] = __float_as_uint(s->As[buf][r][kb]);
                af[mt][1] = __float_as_uint(s->As[buf][r + 8][kb]);
                af[mt][2] = __float_as_uint(s->As[buf][r][kb + 4]);
                af[mt][3] = __float_as_uint(s->As[buf][r + 8][kb + 4]);
            }
            #pragma unroll
            for (int nt = 0; nt < 8; nt++) {
                int nn = wn * 64 + nt * 8 + (lane >> 2);
                bf[nt][0] = __float_as_uint(s->Bs[buf][kb][nn]);
                bf[nt][1] = __float_as_uint(s->Bs[buf][kb + 4][nn]);
            }
            #pragma unroll
            for (int mt = 0; mt < 2; mt++)
                #pragma unroll
                for (int nt = 0; nt < 8; nt++)
                    MMA_TF32(acc[mt][nt], af[mt], bf[nt]);
        }
        __syncthreads();
    }
}

__global__ void __launch_bounds__(256, 2) ctxproj_kernel(const float* __restrict__ b1)
{
    __shared__ SmemT s;
    float acc[2][8][4] = {};
    const int brow = blockIdx.y, bcol = blockIdx.x;
    gemm_core(&s, g_ctxr + (size_t)brow * 128 * HD, HD, g_W1c + bcol * 128, HD, HD, acc);

    const int lane = threadIdx.x & 31;
    const int w = threadIdx.x >> 5, wm = w >> 1, wn = w & 1;
    #pragma unroll
    for (int mt = 0; mt < 2; mt++) {
        #pragma unroll
        for (int nt = 0; nt < 8; nt++) {
            int r = brow * 128 + wm * 32 + mt * 16 + (lane >> 2);
            int c = bcol * 128 + wn * 64 + nt * 8 + 2 * (lane & 3);
            float2 bv = *reinterpret_cast<const float2*>(&b1[c]);
            g_ctxpb[(size_t)r * 256 + (c >> 1)] =
                packbf(acc[mt][nt][0] + bv.x, acc[mt][nt][1] + bv.y);
            g_ctxpb[(size_t)(r + 8) * 256 + (c >> 1)] =
                packbf(acc[mt][nt][2] + bv.x, acc[mt][nt][3] + bv.y);
        }
    }
}

// ================= persistent bf16 step kernel =================
// 8 warps (4m x 2n), warp tile 32x64, CTA tile 128 rows.
struct PS {
    float    zf[128][130];    // fp32 z state           66560 B
    uint32_t zb[128][68];     // bf16x2 z pairs         34816 B
    uint32_t hb[128][68];     // bf16x2 h chunk pairs   34816 B
    uint32_t wb[5][16][136];  // weight slice ring      43520 B
};
#define PS_SZ ((int)sizeof(PS))

extern __shared__ char dynsm[];

__device__ __forceinline__ void mma_slice(
    float acc[2][8][4], const uint32_t (&A)[128][68], int qb,
    const uint32_t (&Bm)[16][136], int lane, int wm, int wn)
{
    #pragma unroll
    for (int kt = 0; kt < 2; kt++) {
        const int qa = qb + kt * 8 + (lane & 3);
        uint32_t af[2][4];
        #pragma unroll
        for (int mt = 0; mt < 2; mt++) {
            int r = wm * 32 + mt * 16 + (lane >> 2);
            af[mt][0] = A[r][qa];
            af[mt][1] = A[r + 8][qa];
            af[mt][2] = A[r][qa + 4];
            af[mt][3] = A[r + 8][qa + 4];
        }
        const int kq = kt * 8 + (lane & 3);
        #pragma unroll
        for (int nt = 0; nt < 8; nt++) {
            int nn = wn * 64 + nt * 8 + (lane >> 2);
            uint32_t b0 = Bm[kq][nn];
            uint32_t b1 = Bm[kq + 4][nn];
            #pragma unroll
            for (int mt = 0; mt < 2; mt++)
                MMA_BF16(acc[mt][nt], af[mt], b0, b1);
        }
    }
}

__global__ void __launch_bounds__(256, 1) step_kernel(
    const float* __restrict__ eps0, const float* __restrict__ eps,
    const float* __restrict__ beta, const float* __restrict__ sigma0,
    const float* __restrict__ b2,   const float* __restrict__ temb,
    const float* __restrict__ tmu)
{
    PS* s = (PS*)dynsm;
    const int tid = threadIdx.x, lane = tid & 31, w = tid >> 5;
    const int wm = w >> 1, wn = w & 1;
    const int grow0 = blockIdx.x * 128;

    const float s0 = sigma0[0];
    const float lg = logf(s0);
    const float dt = 1.0f / TSTEPS;
    double ssum = 0.0;

    // ---- init z (fp32 + bf16 copy) + prior-correction term ----
    {
        float local = 0.f;
        #pragma unroll
        for (int i = 0; i < 16; i++) {
            int lin = (tid + i * 256) * 4;
            int row = lin >> 7, col = lin & 127;
            float4 e = *reinterpret_cast<const float4*>(&eps0[(size_t)(grow0 + row) * ZD + col]);
            float z0 = s0 * e.x, z1 = s0 * e.y, z2 = s0 * e.z, z3 = s0 * e.w;
            s->zf[row][col + 0] = z0; s->zf[row][col + 1] = z1;
            s->zf[row][col + 2] = z2; s->zf[row][col + 3] = z3;
            s->zb[row][(col >> 1) + 0] = packbf(z0, z1);
            s->zb[row][(col >> 1) + 1] = packbf(z2, z3);
            local += 0.5f * (e.x * e.x + e.y * e.y + e.z * e.z + e.w * e.w) + 4.f * lg;
        }
        ssum += (double)local;
    }

    // ---- prologue: prefetch slices 0..3 into ring slots 0..3 ----
    #pragma unroll
    for (int g = 0; g < 4; g++) {
        const uint32_t* src = g_Wsl + (g & 31) * 2048;
        uint32_t dstb = sptr(&s->wb[g % 5][0][0]);
        #pragma unroll
        for (int i = 0; i < 2; i++) {
            int l4 = (tid + i * 256) * 4;
            cp16(dstb + (uint32_t)(((l4 >> 7) * 136 + (l4 & 127)) * 4), src + l4);
        }
        CP_COMMIT();
    }

#define SLICE_PRE(gv) do { \
    asm volatile("cp.async.wait_group 3;" ::: "memory"); \
    __syncthreads(); \
    const uint32_t* _src = g_Wsl + (((gv) + 4) & 31) * 2048; \
    uint32_t _dst = sptr(&s->wb[((gv) + 4) % 5][0][0]); \
    _Pragma("unroll") \
    for (int _i = 0; _i < 2; _i++) { \
        int _l4 = (tid + _i * 256) * 4; \
        cp16(_dst + (uint32_t)(((_l4 >> 7) * 136 + (_l4 & 127)) * 4), _src + _l4); \
    } \
    CP_COMMIT(); \
} while (0)

    int g = 0;
    for (int t = 0; t < TSTEPS; t++) {
        const float beta_f = __ldg(&beta[t]);
        const float beta_b = __ldg(&beta[(t + TSTEPS - 1) % TSTEPS]);
        const float sig_f = sqrtf(2.0f * beta_f * dt) * s0;
        const float sig_b = sqrtf(2.0f * beta_b * dt) * s0;
        const float inv_sb = 1.0f / sig_b;
        const float logdiff = logf(sig_f) - logf(sig_b);

        float accu[2][8][4] = {};

        for (int c = 0; c < 4; c++) {
            float acch[2][8][4] = {};
            #pragma unroll
            for (int kc = 0; kc < 4; kc++) {
                SLICE_PRE(g);
                mma_slice(acch, s->zb, kc * 16, s->wb[g % 5], lane, wm, wn);
                g++;
            }
            // ---- epilogue1: h = bf16(relu(acch + ctxp + te)) -> hb ----
            #pragma unroll
            for (int nt = 0; nt < 8; nt++) {
                int gc = c * 128 + wn * 64 + nt * 8 + 2 * (lane & 3);
                float2 te = *reinterpret_cast<const float2*>(&temb[(size_t)t * HD + gc]);
                int lq = wn * 32 + nt * 4 + (lane & 3);
                #pragma unroll
                for (int mt = 0; mt < 2; mt++) {
                    int r = wm * 32 + mt * 16 + (lane >> 2);
                    #pragma unroll
                    for (int hf = 0; hf < 2; hf++) {
                        int rr = r + 8 * hf;
                        uint32_t cpv = __ldg(&g_ctxpb[(size_t)(grow0 + rr) * 256 + (gc >> 1)]);
                        float v0 = acch[mt][nt][hf * 2 + 0] + bflo(cpv) + te.x;
                        float v1 = acch[mt][nt][hf * 2 + 1] + bfhi(cpv) + te.y;
                        s->hb[rr][lq] = packbf(fmaxf(v0, 0.f), fmaxf(v1, 0.f));
                    }
                }
            }
            #pragma unroll
            for (int kc = 0; kc < 4; kc++) {
                SLICE_PRE(g);
                mma_slice(accu, s->hb, kc * 16, s->wb[g % 5], lane, wm, wn);
                g++;
            }
        }

        // ---- update epilogue ----
        const float* eps_t = eps + ((size_t)t * B_DIM + grow0) * ZD;
        float local = 0.f;
        #pragma unroll
        for (int nt = 0; nt < 8; nt++) {
            int cc = wn * 64 + nt * 8 + 2 * (lane & 3);
            float2 bv = *reinterpret_cast<const float2*>(&b2[cc]);
            #pragma unroll
            for (int mt = 0; mt < 2; mt++) {
                int r = wm * 32 + mt * 16 + (lane >> 2);
                #pragma unroll
                for (int hf = 0; hf < 2; hf++) {
                    int rr = r + 8 * hf;
                    float2 zp = *reinterpret_cast<const float2*>(&s->zf[rr][cc]);
                    float2 ev = *reinterpret_cast<const float2*>(&eps_t[(size_t)rr * ZD + cc]);
                    float u0 = accu[mt][nt][hf * 2 + 0] + bv.x;
                    float u1 = accu[mt][nt][hf * 2 + 1] + bv.y;
                    float mu0 = zp.x + (beta_f * zp.x + u0) * dt;
                    float mu1 = zp.y + (beta_f * zp.y + u1) * dt;
                    float zn0 = fmaf(sig_f, ev.x, mu0);
                    float zn1 = fmaf(sig_f, ev.y, mu1);
                    float mb0 = zn0 - beta_b * zn0 * dt;
                    float mb1 = zn1 - beta_b * zn1 * dt;
                    float a10 = (zp.x - mb0) * inv_sb;
                    float a11 = (zp.y - mb1) * inv_sb;
                    local += 0.5f * (ev.x * ev.x - a10 * a10) + logdiff;
                    local += 0.5f * (ev.y * ev.y - a11 * a11) + logdiff;
                    if (t == TSTEPS - 1) {
                        float2 tm = *reinterpret_cast<const float2*>(
                            &tmu[(size_t)(grow0 + rr) * ZD + cc]);
                        float d0 = zn0 - tm.x, d1 = zn1 - tm.y;
                        local -= 0.5f * (d0 * d0 + d1 * d1);
                    }
                    float2 zo = { zn0, zn1 };
                    *reinterpret_cast<float2*>(&s->zf[rr][cc]) = zo;
                    s->zb[rr][cc >> 1] = packbf(zn0, zn1);
                }
            }
        }
        ssum += (double)local;
    }

    // ---- reduce ----
    asm volatile("cp.async.wait_group 0;" ::: "memory");
    __syncthreads();
    double* red = reinterpret_cast<double*>(&s->wb[0][0][0]);
    red[tid] = ssum;
    __syncthreads();
    for (int st = 128; st > 0; st >>= 1) {
        if (tid < st) red[tid] += red[tid + st];
        __syncthreads();
    }
    if (tid == 0) atomicAdd(&g_sum, red[0]);
}

// ---------------- prep / finalize ----------------
__global__ void prep_w1c(const float* __restrict__ W1)
{
    const int N = HD * HD;
    for (int i = blockIdx.x * blockDim.x + threadIdx.x; i < N; i += gridDim.x * blockDim.x)
        g_W1c[i] = rna(W1[ZD * HD + i]);
}
__global__ void prep_ctx(const float* __restrict__ ctx)
{
    const size_t N = (size_t)B_DIM * HD;
    size_t i0 = (size_t)blockIdx.x * blockDim.x + threadIdx.x;
    if (i0 == 0) g_sum = 0.0;
    for (size_t i = i0; i < N; i += (size_t)gridDim.x * blockDim.x)
        g_ctxr[i] = rna(ctx[i]);
}
// build packed bf16 weight slices: slice si: c=si>>3, ph=(si>>2)&1, kc=si&3
__global__ void prep_slices(const float* __restrict__ W1, const float* __restrict__ W2)
{
    int idx = blockIdx.x * blockDim.x + threadIdx.x;
    if (idx >= 32 * 2048) return;
    int si = idx >> 11, rem = idx & 2047;
    int q = rem >> 7, n = rem & 127;
    int c = si >> 3, ph = (si >> 2) & 1, kc = si & 3;
    float v0, v1;
    if (!ph) {
        int k0 = kc * 32 + 2 * q;
        v0 = W1[(size_t)k0 * HD + c * 128 + n];
        v1 = W1[(size_t)(k0 + 1) * HD + c * 128 + n];
    } else {
        int k0 = c * 128 + kc * 32 + 2 * q;
        v0 = W2[(size_t)k0 * ZD + n];
        v1 = W2[(size_t)(k0 + 1) * ZD + n];
    }
    g_Wsl[idx] = packbf(v0, v1);
}
__global__ void write_out(float* __restrict__ out)
{
    out[0] = (float)(g_sum / (double)B_DIM);
}

// ---------------- host launcher ----------------
extern "C" void kernel_launch(void* const* d_in, const int* in_sizes, int n_in,
                              void* d_out, int out_size)
{
    (void)in_sizes; (void)n_in; (void)out_size;
    const float* ctx    = (const float*)d_in[0];
    const float* eps0   = (const float*)d_in[1];
    const float* eps    = (const float*)d_in[2];
    const float* beta   = (const float*)d_in[3];
    const float* sigma0 = (const float*)d_in[4];
    const float* W1     = (const float*)d_in[5];
    const float* b1     = (const float*)d_in[6];
    const float* W2     = (const float*)d_in[7];
    const float* b2     = (const float*)d_in[8];
    const float* temb   = (const float*)d_in[9];
    const float* tmu    = (const float*)d_in[10];
    float* out = (float*)d_out;

    cudaFuncSetAttribute(step_kernel, cudaFuncAttributeMaxDynamicSharedMemorySize, PS_SZ);

    prep_w1c<<<256, 256>>>(W1);
    prep_ctx<<<2048, 256>>>(ctx);
    prep_slices<<<256, 256>>>(W1, W2);
    ctxproj_kernel<<<dim3(4, 128), 256>>>(b1);
    step_kernel<<<128, 256, PS_SZ>>>(eps0, eps, beta, sigma0, b2, temb, tmu);
    write_out<<<1, 1>>>(out);
}